// round 10
// baseline (speedup 1.0000x reference)
#include <cuda_runtime.h>
#include <cuda_fp16.h>

// IVPLoss: 8-step Euler trajectories of bilinear-sampled vector fields,
// MSE between pred and true trajectories (incl. identity step 0).
//
// R10 = R9 + 2 independent pixel-pairs per traj thread (ILP):
//  thread handles (x, y) and (x, y+384) — two independent dependency
//  chains double per-thread MLP so the L1tex pipe (84.5% in R9, issue
//  67.5%) saturates instead of idling on the serial LDG->lerp->LDG chain.
//  repack: R2 per-pixel gather (best measured, 24us), + padded row/col.
//
// Packed layout per pixel (8B): { half2(c0[x],c1[x]), half2(c0[x+1],c1[x+1]) }
// -> one bilinear sample = 2 coalesced LDG.64 + HFMA2 lerps.

#define Bv 8
#define Hv 768
#define Wv 768
#define WPK 769                      // padded width  (col 768 = col 767)
#define HPK 769                      // padded height (row 768 = row 767)
#define NSTEPS 8
#define DXC 0.5f
#define YOFF 384                     // second pixel's row offset

#define PLANE (Hv * Wv)              // 589824
#define PK_PLANE (HPK * WPK)         // 591361
#define PK_TOTAL (Bv * PK_PLANE)     // 4730888

__device__ uint2 g_pred[PK_TOTAL];
__device__ uint2 g_true[PK_TOTAL];
__device__ double g_acc;

__device__ __forceinline__ unsigned int h2u(__half2 h) {
    return *reinterpret_cast<unsigned int*>(&h);
}

__device__ __forceinline__ uint2 pack_pair(const float* __restrict__ f,
                                           int base, int xs, int x1) {
    __half2 p0 = __floats2half2_rn(__ldg(f + base + xs),
                                   __ldg(f + base + PLANE + xs));
    __half2 p1 = __floats2half2_rn(__ldg(f + base + x1),
                                   __ldg(f + base + PLANE + x1));
    return make_uint2(h2u(p0), h2u(p1));
}

// one thread per packed element (R2 structure; best measured repack)
__global__ __launch_bounds__(256) void repack_kernel(const float* __restrict__ pred,
                                                     const float* __restrict__ tru) {
    int idx = blockIdx.x * blockDim.x + threadIdx.x;
    if (idx == 0) g_acc = 0.0;
    if (idx >= PK_TOTAL) return;
    int x = idx % WPK;
    int rest = idx / WPK;
    int y = rest % HPK;
    int b = rest / HPK;
    int xs = min(x, Wv - 1);                 // padded col duplicates last col
    int x1 = min(xs + 1, Wv - 1);
    int ys = min(y, Hv - 1);                 // padded row duplicates last row
    int base = b * 2 * PLANE + ys * Wv;      // channel-0 row base
    g_pred[idx] = pack_pair(pred, base, xs, x1);
    g_true[idx] = pack_pair(tru,  base, xs, x1);
}

__device__ __forceinline__ float2 bsample(const uint2* __restrict__ P,
                                          float x, float y) {
    // clip to [0, W-1] / [0, H-1] (matches jnp.clip)
    x = fminf(fmaxf(x, 0.0f), (float)(Wv - 1));
    y = fminf(fmaxf(y, 0.0f), (float)(Hv - 1));
    float xf = floorf(x);
    float yf = floorf(y);
    int xi = (int)xf;
    int yi = (int)yf;
    __half2 wx2 = __float2half2_rn(x - xf);
    __half2 wy2 = __float2half2_rn(y - yf);

    int ofs = yi * WPK + xi;
    uint2 r0 = __ldg(P + ofs);
    uint2 r1 = __ldg(P + ofs + WPK);    // padded bottom row: always valid
    __half2 v00 = *reinterpret_cast<__half2*>(&r0.x);
    __half2 v01 = *reinterpret_cast<__half2*>(&r0.y);
    __half2 v10 = *reinterpret_cast<__half2*>(&r1.x);
    __half2 v11 = *reinterpret_cast<__half2*>(&r1.y);

    __half2 top = __hfma2(wx2, __hsub2(v01, v00), v00);
    __half2 bot = __hfma2(wx2, __hsub2(v11, v10), v10);
    __half2 res = __hfma2(wy2, __hsub2(bot, top), top);
    return __half22float2(res);
}

// grid (3, 384, 8), block 256: thread integrates pixels (x,y) and (x,y+384)
__global__ __launch_bounds__(256) void traj_kernel() {
    int x = blockIdx.x * blockDim.x + threadIdx.x;  // 0..767
    int y = blockIdx.y;                              // 0..383
    int b = blockIdx.z;
    const uint2* __restrict__ Pp = g_pred + b * PK_PLANE;
    const uint2* __restrict__ Pt = g_true + b * PK_PLANE;

    // chain A: pixel (x, y); chain B: pixel (x, y+YOFF) — independent
    float apx = (float)x, apy = (float)y;
    float atx = (float)x, aty = (float)y;
    float bpx = (float)x, bpy = (float)(y + YOFF);
    float btx = (float)x, bty = (float)(y + YOFF);
    float acc = 0.0f;

    #pragma unroll
    for (int s = 0; s < NSTEPS; s++) {
        float2 avp = bsample(Pp, apx, apy);
        float2 bvp = bsample(Pp, bpx, bpy);
        float2 avt = bsample(Pt, atx, aty);
        float2 bvt = bsample(Pt, btx, bty);
        apx = fmaf(DXC, avp.x, apx);
        apy = fmaf(DXC, avp.y, apy);
        atx = fmaf(DXC, avt.x, atx);
        aty = fmaf(DXC, avt.y, aty);
        bpx = fmaf(DXC, bvp.x, bpx);
        bpy = fmaf(DXC, bvp.y, bpy);
        btx = fmaf(DXC, bvt.x, btx);
        bty = fmaf(DXC, bvt.y, bty);
        float dax = atx - apx;
        float day = aty - apy;
        float dbx = btx - bpx;
        float dby = bty - bpy;
        acc = fmaf(dax, dax, acc);
        acc = fmaf(day, day, acc);
        acc = fmaf(dbx, dbx, acc);
        acc = fmaf(dby, dby, acc);
    }

    // block reduction: warp shuffle -> shared -> warp0 -> atomicAdd(double)
    float v = acc;
    #pragma unroll
    for (int o = 16; o > 0; o >>= 1)
        v += __shfl_down_sync(0xffffffffu, v, o);

    __shared__ float sred[8];
    int lane = threadIdx.x & 31;
    int wid  = threadIdx.x >> 5;
    if (lane == 0) sred[wid] = v;
    __syncthreads();
    if (wid == 0) {
        v = (lane < 8) ? sred[lane] : 0.0f;
        #pragma unroll
        for (int o = 4; o > 0; o >>= 1)
            v += __shfl_down_sync(0xffffffffu, v, o);
        if (lane == 0) atomicAdd(&g_acc, (double)v);
    }
}

__global__ void finalize_kernel(float* __restrict__ out) {
    const double cnt = (double)(NSTEPS + 1) * Bv * 2 * Hv * Wv;  // 84934656
    *out = (float)(g_acc / cnt);
}

extern "C" void kernel_launch(void* const* d_in, const int* in_sizes, int n_in,
                              void* d_out, int out_size) {
    const float* vf_pred = (const float*)d_in[0];
    const float* vf_true = (const float*)d_in[1];
    float* out = (float*)d_out;

    int rp_blocks = (PK_TOTAL + 255) / 256;
    repack_kernel<<<rp_blocks, 256>>>(vf_pred, vf_true);

    dim3 grid(Wv / 256, Hv / 2, Bv);
    traj_kernel<<<grid, 256>>>();

    finalize_kernel<<<1, 1>>>(out);
}

// round 11
// speedup vs baseline: 1.0352x; 1.0352x over previous
#include <cuda_runtime.h>
#include <cuda_fp16.h>

// IVPLoss: 8-step Euler trajectories of bilinear-sampled vector fields,
// MSE between pred and true trajectories (incl. identity step 0).
//
// R11 = R9 (best: 115.3us) + step-0 specialization:
//  at s=0 both trajectories sit on exact integer grid points (wx=wy=0),
//  so the bilinear reduces bit-exactly to reading v00 — one coalesced
//  LDG.32 per field, no clips/floors/lerps. Steps 1..7 unchanged.
//  repack: R2 per-pixel gather (best measured), padded row+col.
//
// Packed layout per pixel (8B): { half2(c0[x],c1[x]), half2(c0[x+1],c1[x+1]) }
// -> one bilinear sample = 2 coalesced LDG.64 + HFMA2 lerps.

#define Bv 8
#define Hv 768
#define Wv 768
#define WPK 769                      // padded width  (col 768 = col 767)
#define HPK 769                      // padded height (row 768 = row 767)
#define NSTEPS 8
#define DXC 0.5f

#define PLANE (Hv * Wv)              // 589824
#define PK_PLANE (HPK * WPK)         // 591361
#define PK_TOTAL (Bv * PK_PLANE)     // 4730888

__device__ uint2 g_pred[PK_TOTAL];
__device__ uint2 g_true[PK_TOTAL];
__device__ double g_acc;

__device__ __forceinline__ unsigned int h2u(__half2 h) {
    return *reinterpret_cast<unsigned int*>(&h);
}

__device__ __forceinline__ uint2 pack_pair(const float* __restrict__ f,
                                           int base, int xs, int x1) {
    __half2 p0 = __floats2half2_rn(__ldg(f + base + xs),
                                   __ldg(f + base + PLANE + xs));
    __half2 p1 = __floats2half2_rn(__ldg(f + base + x1),
                                   __ldg(f + base + PLANE + x1));
    return make_uint2(h2u(p0), h2u(p1));
}

// one thread per packed element (R2 structure; best measured repack)
__global__ __launch_bounds__(256) void repack_kernel(const float* __restrict__ pred,
                                                     const float* __restrict__ tru) {
    int idx = blockIdx.x * blockDim.x + threadIdx.x;
    if (idx == 0) g_acc = 0.0;
    if (idx >= PK_TOTAL) return;
    int x = idx % WPK;
    int rest = idx / WPK;
    int y = rest % HPK;
    int b = rest / HPK;
    int xs = min(x, Wv - 1);                 // padded col duplicates last col
    int x1 = min(xs + 1, Wv - 1);
    int ys = min(y, Hv - 1);                 // padded row duplicates last row
    int base = b * 2 * PLANE + ys * Wv;      // channel-0 row base
    g_pred[idx] = pack_pair(pred, base, xs, x1);
    g_true[idx] = pack_pair(tru,  base, xs, x1);
}

__device__ __forceinline__ float2 bsample(const uint2* __restrict__ P,
                                          float x, float y) {
    // clip to [0, W-1] / [0, H-1] (matches jnp.clip)
    x = fminf(fmaxf(x, 0.0f), (float)(Wv - 1));
    y = fminf(fmaxf(y, 0.0f), (float)(Hv - 1));
    float xf = floorf(x);
    float yf = floorf(y);
    int xi = (int)xf;
    int yi = (int)yf;
    __half2 wx2 = __float2half2_rn(x - xf);
    __half2 wy2 = __float2half2_rn(y - yf);

    int ofs = yi * WPK + xi;
    uint2 r0 = __ldg(P + ofs);
    uint2 r1 = __ldg(P + ofs + WPK);    // padded bottom row: always valid
    __half2 v00 = *reinterpret_cast<__half2*>(&r0.x);
    __half2 v01 = *reinterpret_cast<__half2*>(&r0.y);
    __half2 v10 = *reinterpret_cast<__half2*>(&r1.x);
    __half2 v11 = *reinterpret_cast<__half2*>(&r1.y);

    __half2 top = __hfma2(wx2, __hsub2(v01, v00), v00);
    __half2 bot = __hfma2(wx2, __hsub2(v11, v10), v10);
    __half2 res = __hfma2(wy2, __hsub2(bot, top), top);
    return __half22float2(res);
}

__global__ __launch_bounds__(256) void traj_kernel() {
    int x = blockIdx.x * blockDim.x + threadIdx.x;  // 0..767
    int y = blockIdx.y;
    int b = blockIdx.z;
    const uint2* __restrict__ Pp = g_pred + b * PK_PLANE;
    const uint2* __restrict__ Pt = g_true + b * PK_PLANE;

    float pxp = (float)x, pyp = (float)y;   // pred trajectory
    float pxt = (float)x, pyt = (float)y;   // true trajectory
    float acc = 0.0f;

    // ---- step 0: exact integer position -> bilinear == v00 (bit-exact) ----
    {
        int ofs0 = y * WPK + x;
        unsigned int wp = __ldg(reinterpret_cast<const unsigned int*>(Pp) + 2 * ofs0);
        unsigned int wt = __ldg(reinterpret_cast<const unsigned int*>(Pt) + 2 * ofs0);
        float2 vp = __half22float2(*reinterpret_cast<__half2*>(&wp));
        float2 vt = __half22float2(*reinterpret_cast<__half2*>(&wt));
        pxp = fmaf(DXC, vp.x, pxp);
        pyp = fmaf(DXC, vp.y, pyp);
        pxt = fmaf(DXC, vt.x, pxt);
        pyt = fmaf(DXC, vt.y, pyt);
        float dx = pxt - pxp;
        float dy = pyt - pyp;
        acc = fmaf(dx, dx, acc);
        acc = fmaf(dy, dy, acc);
    }

    // ---- steps 1..7: full bilinear ----
    #pragma unroll
    for (int s = 1; s < NSTEPS; s++) {
        float2 vp = bsample(Pp, pxp, pyp);
        float2 vt = bsample(Pt, pxt, pyt);
        pxp = fmaf(DXC, vp.x, pxp);
        pyp = fmaf(DXC, vp.y, pyp);
        pxt = fmaf(DXC, vt.x, pxt);
        pyt = fmaf(DXC, vt.y, pyt);
        float dx = pxt - pxp;
        float dy = pyt - pyp;
        acc = fmaf(dx, dx, acc);
        acc = fmaf(dy, dy, acc);
    }

    // block reduction: warp shuffle -> shared -> warp0 -> atomicAdd(double)
    float v = acc;
    #pragma unroll
    for (int o = 16; o > 0; o >>= 1)
        v += __shfl_down_sync(0xffffffffu, v, o);

    __shared__ float sred[8];
    int lane = threadIdx.x & 31;
    int wid  = threadIdx.x >> 5;
    if (lane == 0) sred[wid] = v;
    __syncthreads();
    if (wid == 0) {
        v = (lane < 8) ? sred[lane] : 0.0f;
        #pragma unroll
        for (int o = 4; o > 0; o >>= 1)
            v += __shfl_down_sync(0xffffffffu, v, o);
        if (lane == 0) atomicAdd(&g_acc, (double)v);
    }
}

__global__ void finalize_kernel(float* __restrict__ out) {
    const double cnt = (double)(NSTEPS + 1) * Bv * 2 * Hv * Wv;  // 84934656
    *out = (float)(g_acc / cnt);
}

extern "C" void kernel_launch(void* const* d_in, const int* in_sizes, int n_in,
                              void* d_out, int out_size) {
    const float* vf_pred = (const float*)d_in[0];
    const float* vf_true = (const float*)d_in[1];
    float* out = (float*)d_out;

    int rp_blocks = (PK_TOTAL + 255) / 256;
    repack_kernel<<<rp_blocks, 256>>>(vf_pred, vf_true);

    dim3 grid(Wv / 256, Hv, Bv);
    traj_kernel<<<grid, 256>>>();

    finalize_kernel<<<1, 1>>>(out);
}